// round 8
// baseline (speedup 1.0000x reference)
#include <cuda_runtime.h>
#include <cstdint>

#define B_   256
#define D_   784
#define H_   1024
#define T_   10
#define NCH  18
#define CHLEN 44

#define KNEG (-1.4426950408889634f)   // -log2(e)

typedef unsigned long long ull;

// ---------------- scratch ----------------
__device__ __align__(16) float g_Wt[D_ * H_];          // (-log2e)*W transposed: [D][H]
__device__ __align__(16) float g_Apre[NCH * B_ * H_];  // scaled chunk-start accumulators

// ---------------- helpers ----------------
__device__ __forceinline__ float ex2f(float x) {
    float y; asm("ex2.approx.f32 %0, %1;" : "=f"(y) : "f"(x)); return y;
}
__device__ __forceinline__ float rcpf(float x) {
    float y; asm("rcp.approx.f32 %0, %1;" : "=f"(y) : "f"(x)); return y;
}
__device__ __forceinline__ ull fma2_(ull a, ull b, ull c) {
    ull d; asm("fma.rn.f32x2 %0, %1, %2, %3;" : "=l"(d) : "l"(a), "l"(b), "l"(c)); return d;
}
__device__ __forceinline__ ull pack2_(float lo, float hi) {
    ull d; asm("mov.b64 %0, {%1, %2};" : "=l"(d) : "f"(lo), "f"(hi)); return d;
}
__device__ __forceinline__ void unpack2_(ull v, float& lo, float& hi) {
    asm("mov.b64 {%0, %1}, %2;" : "=f"(lo), "=f"(hi) : "l"(v));
}
__device__ __forceinline__ void cp_async16(float* s, const float* g) {
    unsigned sa = (unsigned)__cvta_generic_to_shared(s);
    asm volatile("cp.async.ca.shared.global [%0], [%1], 16;\n" :: "r"(sa), "l"(g));
}
__device__ __forceinline__ void cp_async8(float* s, const float* g) {
    unsigned sa = (unsigned)__cvta_generic_to_shared(s);
    asm volatile("cp.async.ca.shared.global [%0], [%1], 8;\n" :: "r"(sa), "l"(g));
}
__device__ __forceinline__ void cp_commit() {
    asm volatile("cp.async.commit_group;\n" ::: "memory");
}

// ---------------- K1: transpose W [H][D] -> (-log2e)*Wt [D][H] ----------------
__global__ void k_transW(const float* __restrict__ W) {
    __shared__ float tile[32][33];
    int d = blockIdx.x * 32 + threadIdx.x;
    int h = blockIdx.y * 32 + threadIdx.y;
#pragma unroll
    for (int j = 0; j < 32; j += 8)
        if (d < D_) tile[threadIdx.y + j][threadIdx.x] = W[(h + j) * D_ + d] * KNEG;
    __syncthreads();
    int ho = blockIdx.y * 32 + threadIdx.x;
    int do_ = blockIdx.x * 32 + threadIdx.y;
#pragma unroll
    for (int j = 0; j < 32; j += 8)
        if (do_ + j < D_) g_Wt[(do_ + j) * H_ + ho] = tile[threadIdx.x][threadIdx.y + j];
}

// ---------------- K2: chunk sums ----------------
__global__ __launch_bounds__(512) void k_chunksum(const int* __restrict__ x) {
    int bg = blockIdx.x;
    int k  = blockIdx.y;
    int i0 = k * CHLEN;
    int len = min(CHLEN, D_ - i0);
    __shared__ float xs2[CHLEN * 32];
    int tid = threadIdx.x;
    for (int idx = tid; idx < len * 32; idx += 512) {
        int j = idx >> 5, b = idx & 31;
        xs2[idx] = (float)x[(size_t)(bg * 32 + b) * D_ + i0 + j];
    }
    __syncthreads();
    int h0 = blockIdx.z * 512 + tid;
    float acc[32];
#pragma unroll
    for (int b = 0; b < 32; b++) acc[b] = 0.f;
    float wn1 = g_Wt[i0 * H_ + h0];
    float wn2 = (len > 1) ? g_Wt[(i0 + 1) * H_ + h0] : 0.f;
    for (int j = 0; j < len; j++) {
        float wv = wn1;
        wn1 = wn2;
        if (j + 2 < len) wn2 = g_Wt[(i0 + j + 2) * H_ + h0];
        const float* xr = &xs2[j * 32];
#pragma unroll
        for (int b = 0; b < 32; b++)
            acc[b] = fmaf(xr[b], wv, acc[b]);
    }
#pragma unroll
    for (int b = 0; b < 32; b++)
        g_Apre[(size_t)(k * B_ + bg * 32 + b) * H_ + h0] = acc[b];
}

// ---------------- K3: exclusive prefix (float2, 512 blocks) ----------------
__global__ void k_prefix(const float* __restrict__ c) {
    int idx = blockIdx.x * 256 + threadIdx.x;
    int b  = idx >> 9;
    int h0 = (idx & 511) * 2;
    float2 acc = *(const float2*)&c[h0];
    acc.x *= KNEG; acc.y *= KNEG;
#pragma unroll
    for (int k = 0; k < NCH; k++) {
        float2* p = (float2*)&g_Apre[(size_t)(k * B_ + b) * H_ + h0];
        float2 s = *p;
        *p = acc;
        acc.x += s.x; acc.y += s.y;
    }
}

// ---------------- K4: main fused kernel (2 steps per barrier) ----------------
// smem layout (floats):
#define SM_V   0                       // 4 * 10240 = 40960  (V native [H][10])
#define SM_W   40960                   // 4 * 1024  =  4096
#define SM_BB  (SM_W + 4096)           // 8 * 16    =   128
#define SM_RED (SM_BB + 128)           // 4 * 8*10*32 = 10240
#define SM_FLOATS (SM_RED + 10240)     // 55424 floats = 221696 B

__device__ __forceinline__ void stage(float* sm, int i0, int srel, int tid,
                                      const float* __restrict__ V,
                                      const float* __restrict__ bias) {
    const int i  = i0 + srel;
    const int bb = srel & 3;
    const float* vg = V + (size_t)i * (T_ * H_);
    float* vs = sm + SM_V + bb * (T_ * H_);
#pragma unroll
    for (int q = 0; q < 10; q++)
        cp_async16(vs + (tid + q * 256) * 4, vg + (tid + q * 256) * 4);
    cp_async16(sm + SM_W + bb * H_ + tid * 4, g_Wt + (size_t)i * H_ + tid * 4);
    if (tid < 5)
        cp_async8(sm + SM_BB + (srel & 7) * 16 + tid * 2, bias + (size_t)i * T_ + tid * 2);
}

__device__ __forceinline__ void step_compute(float* sm, ull* a2, float xvf,
                                             int h0, int w, int L, int srel) {
    const int bb = srel & 3;
    const float* Vp = sm + SM_V + bb * (T_ * H_);
    const float* Wp = sm + SM_W + bb * H_;
    const ull x2 = pack2_(xvf, xvf);

    ull acc[5];
#pragma unroll
    for (int j = 0; j < 5; j++) acc[j] = 0ull;

    // 2-wide software-pipelined sigmoid
    float se, so;
    {
        float f0, f1;
        unpack2_(a2[0], f0, f1);
        se = rcpf(1.f + ex2f(f0));
        so = rcpf(1.f + ex2f(f1));
    }

    ulonglong2 wv;
#pragma unroll
    for (int u = 0; u < 64; u++) {          // unit = h-pair (h0+2u, h0+2u+1); h0+2u even
        float ne = 0.f, no = 0.f;
        if (u < 63) {
            float f0, f1;
            unpack2_(a2[u + 1], f0, f1);
            ne = rcpf(1.f + ex2f(f0));
            no = rcpf(1.f + ex2f(f1));
        }
        if ((u & 1) == 0) wv = *(const ulonglong2*)(Wp + h0 + 2 * u);
        a2[u] = fma2_(x2, (u & 1) ? wv.y : wv.x, a2[u]);

        const float* vre = Vp + (h0 + 2 * u) * T_;   // even row: 16B aligned
        const ull sse = pack2_(se, se);
        const ull sso = pack2_(so, so);
        // even row: LDS.128 + LDS.128 + LDS.64
        const ulonglong2 e01 = *(const ulonglong2*)(vre);       // (t0,t1),(t2,t3)
        const ulonglong2 e23 = *(const ulonglong2*)(vre + 4);   // (t4,t5),(t6,t7)
        const ull        e4  = *(const ull*)       (vre + 8);   // (t8,t9)
        acc[0] = fma2_(sse, e01.x, acc[0]);
        acc[1] = fma2_(sse, e01.y, acc[1]);
        acc[2] = fma2_(sse, e23.x, acc[2]);
        acc[3] = fma2_(sse, e23.y, acc[3]);
        acc[4] = fma2_(sse, e4,   acc[4]);
        // odd row (starts at +40B ≡ 8 mod 16): LDS.64 + LDS.128 + LDS.128
        const ull        o0  = *(const ull*)       (vre + 10);  // (t0,t1)
        const ulonglong2 o12 = *(const ulonglong2*)(vre + 12);  // (t2,t3),(t4,t5)
        const ulonglong2 o34 = *(const ulonglong2*)(vre + 16);  // (t6,t7),(t8,t9)
        acc[0] = fma2_(sso, o0,    acc[0]);
        acc[1] = fma2_(sso, o12.x, acc[1]);
        acc[2] = fma2_(sso, o12.y, acc[2]);
        acc[3] = fma2_(sso, o34.x, acc[3]);
        acc[4] = fma2_(sso, o34.y, acc[4]);

        se = ne; so = no;
    }

    float* red = sm + SM_RED + (srel & 3) * 2560;
#pragma unroll
    for (int j = 0; j < 5; j++) {
        float lo, hi;
        unpack2_(acc[j], lo, hi);
        red[(w * T_ + 2 * j)     * 32 + L] = lo;
        red[(w * T_ + 2 * j + 1) * 32 + L] = hi;
    }
}

__device__ __forceinline__ void do_softmax(const float* sm, float* outB, int srel, int L) {
    float l[T_];
#pragma unroll
    for (int t = 0; t < T_; t++) l[t] = sm[SM_BB + (srel & 7) * 16 + t];
    const float* red = sm + SM_RED + (srel & 3) * 2560;
#pragma unroll
    for (int ww = 0; ww < 8; ww++)
#pragma unroll
        for (int t = 0; t < T_; t++)
            l[t] += red[(ww * T_ + t) * 32 + L];
    float mx = l[0];
#pragma unroll
    for (int t = 1; t < T_; t++) mx = fmaxf(mx, l[t]);
    float e[T_]; float sum = 0.f;
#pragma unroll
    for (int t = 0; t < T_; t++) {
        e[t] = ex2f((l[t] - mx) * 1.4426950408889634f);
        sum += e[t];
    }
    const float r = rcpf(sum);
#pragma unroll
    for (int t = 0; t < T_; t++)
        outB[t * D_ + srel] = e[t] * r;
}

__global__ __launch_bounds__(256, 1) void k_main(const int* __restrict__ xi,
                                                 const float* __restrict__ V,
                                                 const float* __restrict__ bias,
                                                 float* __restrict__ out) {
    extern __shared__ float sm[];
    const int tid   = threadIdx.x;
    const int w     = tid >> 5;       // 0..7
    const int L     = tid & 31;       // lane = batch within tile
    const int tile  = blockIdx.x;     // 0..7
    const int chunk = blockIdx.y;     // 0..NCH-1
    const int i0  = chunk * CHLEN;
    const int len = min(CHLEN, D_ - i0);   // 44 or 36 (even)
    const int h0  = w * 128;

    // a (scaled by -log2e) in registers: 128 h as 64 f32x2 pairs; a2[u] = (a_{h0+2u}, a_{h0+2u+1})
    ull a2[64];
    {
        const ulonglong2* ag = (const ulonglong2*)(g_Apre +
            (size_t)(chunk * B_ + tile * 32 + L) * H_ + h0);
#pragma unroll
        for (int g = 0; g < 32; g++) {
            ulonglong2 v = ag[g];
            a2[2 * g]     = v.x;
            a2[2 * g + 1] = v.y;
        }
    }

    stage(sm, i0, 0, tid, V, bias); cp_commit();
    stage(sm, i0, 1, tid, V, bias); cp_commit();

    const int* xrow = xi + (size_t)(tile * 32 + L) * D_ + i0;
    float xa = (float)__ldg(xrow + 0);
    float xb = (float)__ldg(xrow + 1);

    float* outB = out + (size_t)(tile * 32 + L) * (T_ * D_) + i0;

    for (int s = 0; s < len; s += 2) {
        asm volatile("cp.async.wait_group 0;\n" ::: "memory");
        __syncthreads();   // one barrier per 2 steps

        const float xc = xa, xd = xb;
        if (s + 2 < len) {
            xa = (float)__ldg(xrow + s + 2);
            xb = (float)__ldg(xrow + s + 3);
            stage(sm, i0, s + 2, tid, V, bias); cp_commit();
            stage(sm, i0, s + 3, tid, V, bias); cp_commit();
        }

        // deferred softmax for steps s-2, s-1 (two distinct warps, concurrent)
        if (s >= 2) {
            if (w == ((s - 2) & 7)) do_softmax(sm, outB, s - 2, L);
            if (w == ((s - 1) & 7)) do_softmax(sm, outB, s - 1, L);
        }

        step_compute(sm, a2, xc, h0, w, L, s);
        step_compute(sm, a2, xd, h0, w, L, s + 1);
    }

    // epilogue: last two steps' softmax
    __syncthreads();
    if (w == ((len - 2) & 7)) do_softmax(sm, outB, len - 2, L);
    if (w == ((len - 1) & 7)) do_softmax(sm, outB, len - 1, L);
}

// ---------------- launch ----------------
extern "C" void kernel_launch(void* const* d_in, const int* in_sizes, int n_in,
                              void* d_out, int out_size) {
    const int*   x    = (const int*)d_in[0];
    const float* W    = (const float*)d_in[1];
    const float* c    = (const float*)d_in[2];
    const float* V    = (const float*)d_in[3];
    const float* bias = (const float*)d_in[4];
    float* out = (float*)d_out;

    static_assert(SM_FLOATS * 4 <= 232448, "smem budget");
    cudaFuncSetAttribute(k_main, cudaFuncAttributeMaxDynamicSharedMemorySize,
                         SM_FLOATS * (int)sizeof(float));

    k_transW<<<dim3((D_ + 31) / 32, H_ / 32), dim3(32, 8)>>>(W);     // launch 1
    k_chunksum<<<dim3(B_ / 32, NCH, 2), 512>>>(x);                   // launch 2
    k_prefix<<<(B_ * H_ / 2) / 256, 256>>>(c);                       // launch 3
    k_main<<<dim3(B_ / 32, NCH), 256, SM_FLOATS * (int)sizeof(float)>>>(x, V, bias, out);  // launch 4 -> profiled
}